// round 11
// baseline (speedup 1.0000x reference)
#include <cuda_runtime.h>
#include <stdint.h>

// ---------------------------------------------------------------------------
// Problem constants
// ---------------------------------------------------------------------------
#define EE   1000000
#define ND   10000
#define NT   20000
#define NRR  100
#define DD   64
#define SAMP 16
#define CAP  512         // per-head bucket capacity (deg ~ Poisson(100))
#define OVF  65536       // overflow list capacity (guaranteed-correct fallback)

// ---------------------------------------------------------------------------
// Scratch (no allocs allowed -> __device__ globals)
// ---------------------------------------------------------------------------
__device__ unsigned long long g_keys[(size_t)ND * CAP];   // 41 MB bucketed keys
__device__ int                g_cur[ND];                  // bucket cursors == degrees
__device__ int                g_ovf_cnt;
__device__ int                g_ovf_head[OVF];
__device__ unsigned long long g_ovf_key[OVF];
__device__ unsigned int       g_sel[ND * SAMP];           // selected edge ids
__device__ float              g_selscore[ND * SAMP];      // their scores
__device__ float              g_neigh[ND * DD];
__device__ float              g_y[ND * DD];
__device__ float              g_w2rs[DD];
__device__ float              g_b2sum[1];
__device__ double             g_sum[DD];
__device__ double             g_sumsq[DD];
__device__ float              g_scale[DD];
__device__ float              g_shift[DD];

// ---------------------------------------------------------------------------
// Threefry-2x32 (20 rounds) — shared host/device
// ---------------------------------------------------------------------------
__host__ __device__ __forceinline__ void tf2x32(uint32_t k0, uint32_t k1,
                                                uint32_t x0, uint32_t x1,
                                                uint32_t& o0, uint32_t& o1)
{
    uint32_t ks[3];
    ks[0] = k0; ks[1] = k1; ks[2] = k0 ^ k1 ^ 0x1BD11BDAu;
    const int RA[4] = {13, 15, 26, 6};
    const int RB[4] = {17, 29, 16, 24};
    x0 += ks[0]; x1 += ks[1];
#pragma unroll
    for (int g = 0; g < 5; ++g) {
        const int* R = (g & 1) ? RB : RA;
#pragma unroll
        for (int i = 0; i < 4; ++i) {
            x0 += x1;
            int r = R[i];
            x1 = (x1 << r) | (x1 >> (32 - r));
            x1 ^= x0;
        }
        x0 += ks[(g + 1) % 3];
        x1 += ks[(g + 2) % 3] + (uint32_t)(g + 1);
    }
    o0 = x0; o1 = x1;
}

__host__ __device__ __forceinline__ uint32_t jax_bits32(uint32_t k0, uint32_t k1,
                                                        uint32_t hi, uint32_t lo)
{
    uint32_t o0, o1;
    tf2x32(k0, k1, hi, lo, o0, o1);
    return o0 ^ o1;   // _threefry_random_bits_partitionable, bit_width==32
}

// ---------------------------------------------------------------------------
// Packed f32x2 FMA helpers (FFMA2 — 2x fp32 throughput on sm_103a)
// ---------------------------------------------------------------------------
__device__ __forceinline__ unsigned long long pk2(float lo, float hi)
{
    unsigned long long r;
    asm("mov.b64 %0, {%1, %2};" : "=l"(r) : "f"(lo), "f"(hi));
    return r;
}
__device__ __forceinline__ void fma2(unsigned long long& acc,
                                     unsigned long long a, unsigned long long b)
{
    asm("fma.rn.f32x2 %0, %1, %2, %0;" : "+l"(acc) : "l"(a), "l"(b));
}
__device__ __forceinline__ float2 up2(unsigned long long v)
{
    float lo, hi;
    asm("mov.b64 {%0, %1}, %2;" : "=f"(lo), "=f"(hi) : "l"(v));
    return make_float2(lo, hi);
}
__device__ __forceinline__ float sigm(float x)
{
    return 1.f / (1.f + __expf(-x));
}

// ---------------------------------------------------------------------------
// K0: zero cursors, rowsum W2, b2 sum
// ---------------------------------------------------------------------------
__global__ void k_init(const float* __restrict__ W2, const float* __restrict__ b2)
{
    int i = blockIdx.x * blockDim.x + threadIdx.x;
    if (i < ND) g_cur[i] = 0;
    if (i < DD) {
        float s = 0.f;
        for (int j = 0; j < DD; ++j) s += W2[i * DD + j];
        g_w2rs[i] = s;
        g_sum[i] = 0.0; g_sumsq[i] = 0.0;
    }
    if (i == 0) {
        float s = 0.f;
        for (int j = 0; j < DD; ++j) s += b2[j];
        g_b2sum[0] = s;
        g_ovf_cnt = 0;
    }
}

// ---------------------------------------------------------------------------
// K1: single-pass bucketed scatter of sort keys (bits>>9, edge_id).
//     Bucket cursor doubles as the degree count.
// ---------------------------------------------------------------------------
__global__ void k_scatter(const int* __restrict__ dkg, uint32_t ka, uint32_t kb)
{
    int e = blockIdx.x * blockDim.x + threadIdx.x;
    if (e >= EE) return;
    int head = dkg[3 * e];
    uint32_t bits = jax_bits32(ka, kb, 0u, (uint32_t)e);
    uint32_t m = bits >> 9;  // float order == (bits>>9) order
    unsigned long long key =
        ((unsigned long long)m << 32) | (unsigned long long)(uint32_t)e;
    int pos = atomicAdd(&g_cur[head], 1);
    if (pos < CAP) {
        g_keys[(size_t)head * CAP + pos] = key;
    } else {
        int o = atomicAdd(&g_ovf_cnt, 1);
        if (o < OVF) { g_ovf_head[o] = head; g_ovf_key[o] = key; }
    }
}

// ---------------------------------------------------------------------------
// K2: warp-per-drug: select the 16 smallest keys (== rank<16 in lexsort order)
//     and record their edge ids in sorted order.
// ---------------------------------------------------------------------------
__global__ void __launch_bounds__(256) k_select()
{
    int wid = threadIdx.x >> 5, lane = threadIdx.x & 31;
    int d = blockIdx.x * 8 + wid;
    if (d >= ND) return;
    int deg = g_cur[d];
    if (deg <= 0) return;
    int n = min(deg, CAP);
    int oc = min(g_ovf_cnt, OVF);
    int nkeep = min(deg, SAMP);
    const unsigned long long* bucket = g_keys + (size_t)d * CAP;

    unsigned long long prev = 0;
    bool small = (n <= 192) && (oc == 0);
    unsigned long long kreg[6];
    if (small) {
#pragma unroll
        for (int q = 0; q < 6; ++q) {
            int p = lane + q * 32;
            kreg[q] = (p < n) ? bucket[p] : ~0ull;
        }
    }
    for (int it = 0; it < nkeep; ++it) {
        unsigned long long best = ~0ull;
        if (small) {
#pragma unroll
            for (int q = 0; q < 6; ++q) {
                unsigned long long kk = kreg[q];
                if ((it == 0 || kk > prev) && kk < best) best = kk;
            }
        } else {
            for (int p = lane; p < n; p += 32) {
                unsigned long long kk = bucket[p];
                if ((it == 0 || kk > prev) && kk < best) best = kk;
            }
            for (int o = lane; o < oc; o += 32) {
                if (g_ovf_head[o] == d) {
                    unsigned long long kk = g_ovf_key[o];
                    if ((it == 0 || kk > prev) && kk < best) best = kk;
                }
            }
        }
#pragma unroll
        for (int s = 16; s; s >>= 1) {
            unsigned long long o = __shfl_xor_sync(0xffffffffu, best, s);
            if (o < best) best = o;
        }
        prev = best;
        if (lane == 0) g_sel[d * SAMP + it] = (unsigned int)best;
    }
}

// ---------------------------------------------------------------------------
// K3: register-tiled batched GEMM scorer.
//     Block = 128 threads = 128 selected edges.
//     Phase 1: stage h = drug⊙rel transposed into smem sH[k][edge].
//     Phase 2: 16 edge-groups x 8 output-groups; 8x8 microtile per thread,
//              A from smem (conflict-free LDS.128), W1 from global (uniform,
//              L1-resident), f32x2-packed accumulators.
//     Epilogue: sigmoid · rowsum(W2), shfl reduce over output groups.
// ---------------------------------------------------------------------------
__global__ void __launch_bounds__(128) k_score_gemm(const float* __restrict__ drug_emb,
                                                    const float* __restrict__ rel_emb,
                                                    const float* __restrict__ W1,
                                                    const float* __restrict__ b1,
                                                    const int* __restrict__ dkg)
{
    __shared__ float sH[DD][128];   // 32 KB: h transposed, sH[k][edge-in-block]
    __shared__ float sV[128];       // validity flags

    int t = threadIdx.x;
    int base = blockIdx.x * 128;

    // ---- Phase 1: gather + stage ----
    {
        int idx = base + t;                 // < ND*SAMP always (1250*128 == 160000)
        int d = idx >> 4, i = idx & 15;
        int nk = min(g_cur[d], SAMP);
        bool valid = (i < nk);
        unsigned int e = valid ? g_sel[idx] : 0u;
        int rel = dkg[3 * (int)e + 2];
        const float4* dp = (const float4*)(drug_emb + (size_t)d * DD);
        const float4* rp = (const float4*)(rel_emb + (size_t)rel * DD);
        float m = valid ? 1.f : 0.f;
#pragma unroll
        for (int q = 0; q < 16; ++q) {
            float4 a = dp[q], b = rp[q];
            sH[4 * q + 0][t] = m * a.x * b.x;
            sH[4 * q + 1][t] = m * a.y * b.y;
            sH[4 * q + 2][t] = m * a.z * b.z;
            sH[4 * q + 3][t] = m * a.w * b.w;
        }
        sV[t] = m;
    }
    __syncthreads();

    // ---- Phase 2: 8x8 microtile GEMM ----
    int tx = t & 7;        // output group: outputs tx*8 .. tx*8+7
    int ty = t >> 3;       // edge group:   edges  ty*8 .. ty*8+7

    unsigned long long acc[8][4];
    {
        const float4* bp = (const float4*)(b1 + tx * 8);
        float4 bv0 = bp[0], bv1 = bp[1];
        unsigned long long i0 = pk2(bv0.x, bv0.y), i1 = pk2(bv0.z, bv0.w);
        unsigned long long i2 = pk2(bv1.x, bv1.y), i3 = pk2(bv1.z, bv1.w);
#pragma unroll
        for (int e = 0; e < 8; ++e) {
            acc[e][0] = i0; acc[e][1] = i1; acc[e][2] = i2; acc[e][3] = i3;
        }
    }

    const float* wbase = W1 + tx * 8;
#pragma unroll 4
    for (int kk = 0; kk < DD; ++kk) {
        float4 a0 = *(const float4*)&sH[kk][ty * 8];
        float4 a1 = *(const float4*)&sH[kk][ty * 8 + 4];
        ulonglong2 w0 = *(const ulonglong2*)(wbase + kk * DD);
        ulonglong2 w1 = *(const ulonglong2*)(wbase + kk * DD + 4);
        float ae[8] = {a0.x, a0.y, a0.z, a0.w, a1.x, a1.y, a1.z, a1.w};
#pragma unroll
        for (int e = 0; e < 8; ++e) {
            unsigned long long aa = pk2(ae[e], ae[e]);
            fma2(acc[e][0], aa, w0.x);
            fma2(acc[e][1], aa, w0.y);
            fma2(acc[e][2], aa, w1.x);
            fma2(acc[e][3], aa, w1.y);
        }
    }

    // ---- Epilogue: sigmoid · rowsum(W2), reduce across the 8 output groups ----
    float rs[8];
    {
        const float4* rp = (const float4*)(g_w2rs + tx * 8);
        float4 r0 = rp[0], r1 = rp[1];
        rs[0] = r0.x; rs[1] = r0.y; rs[2] = r0.z; rs[3] = r0.w;
        rs[4] = r1.x; rs[5] = r1.y; rs[6] = r1.z; rs[7] = r1.w;
    }
    float b2s = g_b2sum[0];

#pragma unroll
    for (int e = 0; e < 8; ++e) {
        float pe = 0.f;
#pragma unroll
        for (int p = 0; p < 4; ++p) {
            float2 uv = up2(acc[e][p]);
            pe += sigm(uv.x) * rs[2 * p] + sigm(uv.y) * rs[2 * p + 1];
        }
        pe += __shfl_xor_sync(0xffffffffu, pe, 1);
        pe += __shfl_xor_sync(0xffffffffu, pe, 2);
        pe += __shfl_xor_sync(0xffffffffu, pe, 4);
        if (tx == 0) {
            int le = ty * 8 + e;
            g_selscore[base + le] = (sV[le] != 0.f) ? (pe + b2s) : 0.f;
        }
    }
}

// ---------------------------------------------------------------------------
// K4: warp-per-drug: neigh[d] = sum_{i<nkeep} score_i * tail_emb[tail_i]
//     (+ with-replacement extras when deg < 16; unreachable at Poisson(100))
// ---------------------------------------------------------------------------
__global__ void __launch_bounds__(256) k_neigh(const int* __restrict__ dkg,
                                               const float* __restrict__ tail_emb,
                                               uint32_t ua, uint32_t ub,
                                               uint32_t uc, uint32_t ud)
{
    int wid = threadIdx.x >> 5, lane = threadIdx.x & 31;
    int d = blockIdx.x * 8 + wid;
    if (d >= ND) return;
    int deg = g_cur[d];
    int nkeep = min(deg, SAMP);
    float ax = 0.f, ay = 0.f;

    for (int i = 0; i < nkeep; ++i) {
        unsigned int e = g_sel[d * SAMP + i];
        float sc = g_selscore[d * SAMP + i];
        int tl = dkg[3 * (int)e + 1];
        float2 te = *(const float2*)(tail_emb + (size_t)tl * DD + 2 * lane);
        ax += sc * te.x; ay += sc * te.y;
    }
    if (deg > 0 && deg < SAMP) {
        int need = SAMP - deg;
        const uint32_t span = 2147483647u;
        for (int si = 0; si < need; ++si) {
            uint32_t flat = (uint32_t)(d * SAMP + si);
            uint32_t hi  = jax_bits32(ua, ub, 0u, flat);
            uint32_t lo2 = jax_bits32(uc, ud, 0u, flat);
            unsigned long long offv =
                ((unsigned long long)(hi % span) * 2ull + (lo2 % span)) % span;
            unsigned int j = (unsigned int)(offv % (unsigned int)deg);
            unsigned int e = g_sel[d * SAMP + j];
            float sc = g_selscore[d * SAMP + j];
            int tl = dkg[3 * (int)e + 1];
            float2 te = *(const float2*)(tail_emb + (size_t)tl * DD + 2 * lane);
            ax += sc * te.x; ay += sc * te.y;
        }
    }
    g_neigh[d * DD + 2 * lane]     = ax;
    g_neigh[d * DD + 2 * lane + 1] = ay;
}

// ---------------------------------------------------------------------------
// K5: y = [drug_emb | neigh] @ Wc + bc, plus per-column sum/sumsq for BN
// ---------------------------------------------------------------------------
__global__ void __launch_bounds__(256) k_y(const float* __restrict__ drug_emb,
                                           const float* __restrict__ Wc,
                                           const float* __restrict__ bc)
{
    __shared__ float sWc[2 * DD * DD];   // 32 KB
    __shared__ float sb[DD];
    __shared__ float red[256];
    int t = threadIdx.x;
    for (int i = t; i < 2 * DD * DD; i += 256) sWc[i] = Wc[i];
    if (t < DD) sb[t] = bc[t];
    __syncthreads();

    int col = t & 63, grp = t >> 6;
    int base = blockIdx.x * 64;
    float s1 = 0.f, s2 = 0.f;
    for (int rr = 0; rr < 16; ++rr) {
        int row = base + rr * 4 + grp;
        if (row < ND) {
            const float* de = drug_emb + (size_t)row * DD;
            const float* ne = g_neigh + (size_t)row * DD;
            float a = sb[col];
#pragma unroll
            for (int i = 0; i < DD; ++i) a += de[i] * sWc[i * DD + col];
#pragma unroll
            for (int i = 0; i < DD; ++i) a += ne[i] * sWc[(DD + i) * DD + col];
            g_y[row * DD + col] = a;
            s1 += a; s2 += a * a;
        }
    }
    red[t] = s1; __syncthreads();
    if (t < 64)
        atomicAdd(&g_sum[t], (double)(red[t] + red[t + 64] + red[t + 128] + red[t + 192]));
    __syncthreads();
    red[t] = s2; __syncthreads();
    if (t < 64)
        atomicAdd(&g_sumsq[t], (double)(red[t] + red[t + 64] + red[t + 128] + red[t + 192]));
}

// ---------------------------------------------------------------------------
// K6: fold BN stats into scale/shift
// ---------------------------------------------------------------------------
__global__ void k_bn(const float* __restrict__ gamma, const float* __restrict__ beta)
{
    int t = threadIdx.x;
    if (t < DD) {
        double mean = g_sum[t] / (double)ND;
        double var = g_sumsq[t] / (double)ND - mean * mean;
        float sc = gamma[t] * rsqrtf((float)var + 1e-5f);
        g_scale[t] = sc;
        g_shift[t] = beta[t] - (float)mean * sc;
    }
}

// ---------------------------------------------------------------------------
// K7: assemble output (HFEmbeding | normalized y | X)
// ---------------------------------------------------------------------------
__global__ void k_out(const float* __restrict__ hfe, const float* __restrict__ X,
                      float* __restrict__ out, int out_size)
{
    int i = blockIdx.x * blockDim.x + threadIdx.x;
    if (i >= out_size) return;
    if (i < ND * DD) {
        out[i] = hfe[i];
    } else if (i < 2 * ND * DD) {
        int j = i - ND * DD;
        int c = j & 63;
        out[i] = g_y[j] * g_scale[c] + g_shift[c];
    } else {
        out[i] = X[i - 2 * ND * DD];
    }
}

// ---------------------------------------------------------------------------
// Launcher
// ---------------------------------------------------------------------------
extern "C" void kernel_launch(void* const* d_in, const int* in_sizes, int n_in,
                              void* d_out, int out_size)
{
    const float* HFE      = (const float*)d_in[0];
    const float* X        = (const float*)d_in[1];
    const float* drug_emb = (const float*)d_in[2];
    const float* rel_emb  = (const float*)d_in[3];
    const float* tail_emb = (const float*)d_in[4];
    const float* W1       = (const float*)d_in[5];
    const float* b1       = (const float*)d_in[6];
    const float* W2       = (const float*)d_in[7];
    const float* b2       = (const float*)d_in[8];
    const float* Wc       = (const float*)d_in[9];
    const float* bc       = (const float*)d_in[10];
    const float* gamma    = (const float*)d_in[11];
    const float* beta     = (const float*)d_in[12];
    const int*   dkg      = (const int*)d_in[13];

    // Derive jax.random.key(42) subkeys on host (pure arithmetic).
    uint32_t key0 = 0u, key1 = 42u;
    uint32_t k1a, k1b, k2a, k2b;
    tf2x32(key0, key1, 0u, 0u, k1a, k1b);   // fold-like split -> subkey 0
    tf2x32(key0, key1, 0u, 1u, k2a, k2b);   // fold-like split -> subkey 1
    // split(k2) for the randint double-draw (dead path: deg>=16 a.s.)
    uint32_t r1a, r1b, r2a, r2b;
    tf2x32(k2a, k2b, 0u, 0u, r1a, r1b);
    tf2x32(k2a, k2b, 0u, 1u, r2a, r2b);

    k_init<<<40, 256>>>(W2, b2);
    k_scatter<<<(EE + 255) / 256, 256>>>(dkg, k1a, k1b);
    k_select<<<(ND + 7) / 8, 256>>>();
    k_score_gemm<<<(ND * SAMP) / 128, 128>>>(drug_emb, rel_emb, W1, b1, dkg);
    k_neigh<<<(ND + 7) / 8, 256>>>(dkg, tail_emb, r1a, r1b, r2a, r2b);
    k_y<<<(ND + 63) / 64, 256>>>(drug_emb, Wc, bc);
    k_bn<<<1, 64>>>(gamma, beta);
    k_out<<<(out_size + 255) / 256, 256>>>(HFE, X, (float*)d_out, out_size);
}

// round 12
// speedup vs baseline: 1.6843x; 1.6843x over previous
#include <cuda_runtime.h>
#include <stdint.h>

// ---------------------------------------------------------------------------
// Problem constants
// ---------------------------------------------------------------------------
#define EE   1000000
#define ND   10000
#define NT   20000
#define NRR  100
#define DD   64
#define SAMP 16
#define CAP  512         // per-head bucket capacity (deg ~ Poisson(100))
#define OVF  65536       // overflow list capacity (guaranteed-correct fallback)

// ---------------------------------------------------------------------------
// Scratch (no allocs allowed -> __device__ globals)
// ---------------------------------------------------------------------------
__device__ unsigned long long g_keys[(size_t)ND * CAP];   // 41 MB bucketed keys
__device__ int                g_cur[ND];                  // bucket cursors == degrees
__device__ int                g_ovf_cnt;
__device__ int                g_ovf_head[OVF];
__device__ unsigned long long g_ovf_key[OVF];
__device__ unsigned int       g_sel[ND * SAMP];           // selected edge ids
__device__ float              g_selscore[ND * SAMP];      // their scores
__device__ float              g_neigh[ND * DD];
__device__ float              g_y[ND * DD];
__device__ float              g_w2rs[DD];
__device__ float              g_b2sum[1];
__device__ double             g_sum[DD];
__device__ double             g_sumsq[DD];
__device__ float              g_scale[DD];
__device__ float              g_shift[DD];

// ---------------------------------------------------------------------------
// Threefry-2x32 (20 rounds) — shared host/device
// ---------------------------------------------------------------------------
__host__ __device__ __forceinline__ void tf2x32(uint32_t k0, uint32_t k1,
                                                uint32_t x0, uint32_t x1,
                                                uint32_t& o0, uint32_t& o1)
{
    uint32_t ks[3];
    ks[0] = k0; ks[1] = k1; ks[2] = k0 ^ k1 ^ 0x1BD11BDAu;
    const int RA[4] = {13, 15, 26, 6};
    const int RB[4] = {17, 29, 16, 24};
    x0 += ks[0]; x1 += ks[1];
#pragma unroll
    for (int g = 0; g < 5; ++g) {
        const int* R = (g & 1) ? RB : RA;
#pragma unroll
        for (int i = 0; i < 4; ++i) {
            x0 += x1;
            int r = R[i];
            x1 = (x1 << r) | (x1 >> (32 - r));
            x1 ^= x0;
        }
        x0 += ks[(g + 1) % 3];
        x1 += ks[(g + 2) % 3] + (uint32_t)(g + 1);
    }
    o0 = x0; o1 = x1;
}

__host__ __device__ __forceinline__ uint32_t jax_bits32(uint32_t k0, uint32_t k1,
                                                        uint32_t hi, uint32_t lo)
{
    uint32_t o0, o1;
    tf2x32(k0, k1, hi, lo, o0, o1);
    return o0 ^ o1;   // _threefry_random_bits_partitionable, bit_width==32
}

// ---------------------------------------------------------------------------
// Packed f32x2 FMA helpers (FFMA2 — 2x fp32 throughput on sm_103a)
// ---------------------------------------------------------------------------
__device__ __forceinline__ unsigned long long pk2(float lo, float hi)
{
    unsigned long long r;
    asm("mov.b64 %0, {%1, %2};" : "=l"(r) : "f"(lo), "f"(hi));
    return r;
}
__device__ __forceinline__ void fma2(unsigned long long& acc,
                                     unsigned long long a, unsigned long long b)
{
    asm("fma.rn.f32x2 %0, %1, %2, %0;" : "+l"(acc) : "l"(a), "l"(b));
}
__device__ __forceinline__ float2 up2(unsigned long long v)
{
    float lo, hi;
    asm("mov.b64 {%0, %1}, %2;" : "=f"(lo), "=f"(hi) : "l"(v));
    return make_float2(lo, hi);
}
__device__ __forceinline__ float sigm(float x)
{
    return 1.f / (1.f + __expf(-x));
}

// ---------------------------------------------------------------------------
// K0: zero cursors, rowsum W2, b2 sum
// ---------------------------------------------------------------------------
__global__ void k_init(const float* __restrict__ W2, const float* __restrict__ b2)
{
    int i = blockIdx.x * blockDim.x + threadIdx.x;
    if (i < ND) g_cur[i] = 0;
    if (i < DD) {
        float s = 0.f;
        for (int j = 0; j < DD; ++j) s += W2[i * DD + j];
        g_w2rs[i] = s;
        g_sum[i] = 0.0; g_sumsq[i] = 0.0;
    }
    if (i == 0) {
        float s = 0.f;
        for (int j = 0; j < DD; ++j) s += b2[j];
        g_b2sum[0] = s;
        g_ovf_cnt = 0;
    }
}

// ---------------------------------------------------------------------------
// K1: single-pass bucketed scatter of sort keys (bits>>9, edge_id).
//     Bucket cursor doubles as the degree count.
// ---------------------------------------------------------------------------
__global__ void k_scatter(const int* __restrict__ dkg, uint32_t ka, uint32_t kb)
{
    int e = blockIdx.x * blockDim.x + threadIdx.x;
    if (e >= EE) return;
    int head = dkg[3 * e];
    uint32_t bits = jax_bits32(ka, kb, 0u, (uint32_t)e);
    uint32_t m = bits >> 9;  // float order == (bits>>9) order
    unsigned long long key =
        ((unsigned long long)m << 32) | (unsigned long long)(uint32_t)e;
    int pos = atomicAdd(&g_cur[head], 1);
    if (pos < CAP) {
        g_keys[(size_t)head * CAP + pos] = key;
    } else {
        int o = atomicAdd(&g_ovf_cnt, 1);
        if (o < OVF) { g_ovf_head[o] = head; g_ovf_key[o] = key; }
    }
}

// ---------------------------------------------------------------------------
// K2: warp-per-drug: select the 16 smallest keys (== rank<16 in lexsort order)
//     and record their edge ids in sorted order.
// ---------------------------------------------------------------------------
__global__ void __launch_bounds__(256) k_select()
{
    int wid = threadIdx.x >> 5, lane = threadIdx.x & 31;
    int d = blockIdx.x * 8 + wid;
    if (d >= ND) return;
    int deg = g_cur[d];
    if (deg <= 0) return;
    int n = min(deg, CAP);
    int oc = min(g_ovf_cnt, OVF);
    int nkeep = min(deg, SAMP);
    const unsigned long long* bucket = g_keys + (size_t)d * CAP;

    unsigned long long prev = 0;
    bool small = (n <= 192) && (oc == 0);
    unsigned long long kreg[6];
    if (small) {
#pragma unroll
        for (int q = 0; q < 6; ++q) {
            int p = lane + q * 32;
            kreg[q] = (p < n) ? bucket[p] : ~0ull;
        }
    }
    for (int it = 0; it < nkeep; ++it) {
        unsigned long long best = ~0ull;
        if (small) {
#pragma unroll
            for (int q = 0; q < 6; ++q) {
                unsigned long long kk = kreg[q];
                if ((it == 0 || kk > prev) && kk < best) best = kk;
            }
        } else {
            for (int p = lane; p < n; p += 32) {
                unsigned long long kk = bucket[p];
                if ((it == 0 || kk > prev) && kk < best) best = kk;
            }
            for (int o = lane; o < oc; o += 32) {
                if (g_ovf_head[o] == d) {
                    unsigned long long kk = g_ovf_key[o];
                    if ((it == 0 || kk > prev) && kk < best) best = kk;
                }
            }
        }
#pragma unroll
        for (int s = 16; s; s >>= 1) {
            unsigned long long o = __shfl_xor_sync(0xffffffffu, best, s);
            if (o < best) best = o;
        }
        prev = best;
        if (lane == 0) g_sel[d * SAMP + it] = (unsigned int)best;
    }
}

// ---------------------------------------------------------------------------
// K3: register-tiled batched GEMM scorer, ALL operands from smem.
//     Block = 128 threads = 64 selected edges.
//     Phase 1: load W1 (16KB) + stage h = drug⊙rel transposed into sH[k][edge]
//              (2 threads per edge).
//     Phase 2: 16 output-groups x 8 edge-groups; 8 edges x 4 outputs per
//              thread, f32x2-packed accumulators.
//              Per k-step: 2 LDS.128 (A) + 1 LDS.128 (W) + 16 FFMA2.
//     Epilogue: sigmoid · rowsum(W2), shfl reduce over 16 output groups.
// ---------------------------------------------------------------------------
__global__ void __launch_bounds__(128) k_score_gemm(const float* __restrict__ drug_emb,
                                                    const float* __restrict__ rel_emb,
                                                    const float* __restrict__ W1,
                                                    const float* __restrict__ b1,
                                                    const int* __restrict__ dkg)
{
    __shared__ float sH[DD][64];    // 16 KB: h transposed, sH[k][edge-in-block]
    __shared__ float sW[DD * DD];   // 16 KB: W1 row-major
    __shared__ float sV[64];        // validity flags

    int t = threadIdx.x;
    int base = blockIdx.x * 64;

    // ---- load W1 into smem ----
#pragma unroll
    for (int i = t; i < DD * DD / 4; i += 128)
        ((float4*)sW)[i] = ((const float4*)W1)[i];

    // ---- Phase 1: gather + stage (2 threads per edge) ----
    {
        int le = t >> 1;            // local edge 0..63
        int half = t & 1;           // which 32 of the 64 dims
        int idx = base + le;        // < ND*SAMP always (2500*64 == 160000)
        int d = idx >> 4, i = idx & 15;
        int nk = min(g_cur[d], SAMP);
        bool valid = (i < nk);
        unsigned int e = valid ? g_sel[idx] : 0u;
        int rel = dkg[3 * (int)e + 2];
        const float4* dp = (const float4*)(drug_emb + (size_t)d * DD) + half * 8;
        const float4* rp = (const float4*)(rel_emb + (size_t)rel * DD) + half * 8;
        float m = valid ? 1.f : 0.f;
#pragma unroll
        for (int q = 0; q < 8; ++q) {
            float4 a = dp[q], b = rp[q];
            int k0 = half * 32 + 4 * q;
            sH[k0 + 0][le] = m * a.x * b.x;
            sH[k0 + 1][le] = m * a.y * b.y;
            sH[k0 + 2][le] = m * a.z * b.z;
            sH[k0 + 3][le] = m * a.w * b.w;
        }
        if (half == 0) sV[le] = m;
    }
    __syncthreads();

    // ---- Phase 2: 8x4 microtile GEMM ----
    int tx = t & 15;       // output group: outputs tx*4 .. tx*4+3
    int ty = t >> 4;       // edge group:   edges  ty*8 .. ty*8+7

    unsigned long long acc[8][2];
    {
        float4 bv = *(const float4*)(b1 + tx * 4);
        unsigned long long i0 = pk2(bv.x, bv.y), i1 = pk2(bv.z, bv.w);
#pragma unroll
        for (int e = 0; e < 8; ++e) { acc[e][0] = i0; acc[e][1] = i1; }
    }

#pragma unroll 4
    for (int kk = 0; kk < DD; ++kk) {
        float4 a0 = *(const float4*)&sH[kk][ty * 8];
        float4 a1 = *(const float4*)&sH[kk][ty * 8 + 4];
        ulonglong2 w = *(const ulonglong2*)(sW + kk * DD + tx * 4);
        float ae[8] = {a0.x, a0.y, a0.z, a0.w, a1.x, a1.y, a1.z, a1.w};
#pragma unroll
        for (int e = 0; e < 8; ++e) {
            unsigned long long aa = pk2(ae[e], ae[e]);
            fma2(acc[e][0], aa, w.x);
            fma2(acc[e][1], aa, w.y);
        }
    }

    // ---- Epilogue: sigmoid · rowsum(W2), reduce across the 16 output groups ----
    float4 rsv = *(const float4*)(g_w2rs + tx * 4);
    float b2s = g_b2sum[0];

#pragma unroll
    for (int e = 0; e < 8; ++e) {
        float2 u0 = up2(acc[e][0]);
        float2 u1 = up2(acc[e][1]);
        float pe = sigm(u0.x) * rsv.x + sigm(u0.y) * rsv.y
                 + sigm(u1.x) * rsv.z + sigm(u1.y) * rsv.w;
        pe += __shfl_xor_sync(0xffffffffu, pe, 1);
        pe += __shfl_xor_sync(0xffffffffu, pe, 2);
        pe += __shfl_xor_sync(0xffffffffu, pe, 4);
        pe += __shfl_xor_sync(0xffffffffu, pe, 8);
        if (tx == 0) {
            int le = ty * 8 + e;
            g_selscore[base + le] = (sV[le] != 0.f) ? (pe + b2s) : 0.f;
        }
    }
}

// ---------------------------------------------------------------------------
// K4: warp-per-drug: neigh[d] = sum_{i<nkeep} score_i * tail_emb[tail_i]
//     (+ with-replacement extras when deg < 16; unreachable at Poisson(100))
// ---------------------------------------------------------------------------
__global__ void __launch_bounds__(256) k_neigh(const int* __restrict__ dkg,
                                               const float* __restrict__ tail_emb,
                                               uint32_t ua, uint32_t ub,
                                               uint32_t uc, uint32_t ud)
{
    int wid = threadIdx.x >> 5, lane = threadIdx.x & 31;
    int d = blockIdx.x * 8 + wid;
    if (d >= ND) return;
    int deg = g_cur[d];
    int nkeep = min(deg, SAMP);
    float ax = 0.f, ay = 0.f;

    for (int i = 0; i < nkeep; ++i) {
        unsigned int e = g_sel[d * SAMP + i];
        float sc = g_selscore[d * SAMP + i];
        int tl = dkg[3 * (int)e + 1];
        float2 te = *(const float2*)(tail_emb + (size_t)tl * DD + 2 * lane);
        ax += sc * te.x; ay += sc * te.y;
    }
    if (deg > 0 && deg < SAMP) {
        int need = SAMP - deg;
        const uint32_t span = 2147483647u;
        for (int si = 0; si < need; ++si) {
            uint32_t flat = (uint32_t)(d * SAMP + si);
            uint32_t hi  = jax_bits32(ua, ub, 0u, flat);
            uint32_t lo2 = jax_bits32(uc, ud, 0u, flat);
            unsigned long long offv =
                ((unsigned long long)(hi % span) * 2ull + (lo2 % span)) % span;
            unsigned int j = (unsigned int)(offv % (unsigned int)deg);
            unsigned int e = g_sel[d * SAMP + j];
            float sc = g_selscore[d * SAMP + j];
            int tl = dkg[3 * (int)e + 1];
            float2 te = *(const float2*)(tail_emb + (size_t)tl * DD + 2 * lane);
            ax += sc * te.x; ay += sc * te.y;
        }
    }
    g_neigh[d * DD + 2 * lane]     = ax;
    g_neigh[d * DD + 2 * lane + 1] = ay;
}

// ---------------------------------------------------------------------------
// K5: y = [drug_emb | neigh] @ Wc + bc, plus per-column sum/sumsq for BN
// ---------------------------------------------------------------------------
__global__ void __launch_bounds__(256) k_y(const float* __restrict__ drug_emb,
                                           const float* __restrict__ Wc,
                                           const float* __restrict__ bc)
{
    __shared__ float sWc[2 * DD * DD];   // 32 KB
    __shared__ float sb[DD];
    __shared__ float red[256];
    int t = threadIdx.x;
    for (int i = t; i < 2 * DD * DD; i += 256) sWc[i] = Wc[i];
    if (t < DD) sb[t] = bc[t];
    __syncthreads();

    int col = t & 63, grp = t >> 6;
    int base = blockIdx.x * 64;
    float s1 = 0.f, s2 = 0.f;
    for (int rr = 0; rr < 16; ++rr) {
        int row = base + rr * 4 + grp;
        if (row < ND) {
            const float* de = drug_emb + (size_t)row * DD;
            const float* ne = g_neigh + (size_t)row * DD;
            float a = sb[col];
#pragma unroll
            for (int i = 0; i < DD; ++i) a += de[i] * sWc[i * DD + col];
#pragma unroll
            for (int i = 0; i < DD; ++i) a += ne[i] * sWc[(DD + i) * DD + col];
            g_y[row * DD + col] = a;
            s1 += a; s2 += a * a;
        }
    }
    red[t] = s1; __syncthreads();
    if (t < 64)
        atomicAdd(&g_sum[t], (double)(red[t] + red[t + 64] + red[t + 128] + red[t + 192]));
    __syncthreads();
    red[t] = s2; __syncthreads();
    if (t < 64)
        atomicAdd(&g_sumsq[t], (double)(red[t] + red[t + 64] + red[t + 128] + red[t + 192]));
}

// ---------------------------------------------------------------------------
// K6: fold BN stats into scale/shift
// ---------------------------------------------------------------------------
__global__ void k_bn(const float* __restrict__ gamma, const float* __restrict__ beta)
{
    int t = threadIdx.x;
    if (t < DD) {
        double mean = g_sum[t] / (double)ND;
        double var = g_sumsq[t] / (double)ND - mean * mean;
        float sc = gamma[t] * rsqrtf((float)var + 1e-5f);
        g_scale[t] = sc;
        g_shift[t] = beta[t] - (float)mean * sc;
    }
}

// ---------------------------------------------------------------------------
// K7: assemble output (HFEmbeding | normalized y | X)
// ---------------------------------------------------------------------------
__global__ void k_out(const float* __restrict__ hfe, const float* __restrict__ X,
                      float* __restrict__ out, int out_size)
{
    int i = blockIdx.x * blockDim.x + threadIdx.x;
    if (i >= out_size) return;
    if (i < ND * DD) {
        out[i] = hfe[i];
    } else if (i < 2 * ND * DD) {
        int j = i - ND * DD;
        int c = j & 63;
        out[i] = g_y[j] * g_scale[c] + g_shift[c];
    } else {
        out[i] = X[i - 2 * ND * DD];
    }
}

// ---------------------------------------------------------------------------
// Launcher
// ---------------------------------------------------------------------------
extern "C" void kernel_launch(void* const* d_in, const int* in_sizes, int n_in,
                              void* d_out, int out_size)
{
    const float* HFE      = (const float*)d_in[0];
    const float* X        = (const float*)d_in[1];
    const float* drug_emb = (const float*)d_in[2];
    const float* rel_emb  = (const float*)d_in[3];
    const float* tail_emb = (const float*)d_in[4];
    const float* W1       = (const float*)d_in[5];
    const float* b1       = (const float*)d_in[6];
    const float* W2       = (const float*)d_in[7];
    const float* b2       = (const float*)d_in[8];
    const float* Wc       = (const float*)d_in[9];
    const float* bc       = (const float*)d_in[10];
    const float* gamma    = (const float*)d_in[11];
    const float* beta     = (const float*)d_in[12];
    const int*   dkg      = (const int*)d_in[13];

    // Derive jax.random.key(42) subkeys on host (pure arithmetic).
    uint32_t key0 = 0u, key1 = 42u;
    uint32_t k1a, k1b, k2a, k2b;
    tf2x32(key0, key1, 0u, 0u, k1a, k1b);   // fold-like split -> subkey 0
    tf2x32(key0, key1, 0u, 1u, k2a, k2b);   // fold-like split -> subkey 1
    // split(k2) for the randint double-draw (dead path: deg>=16 a.s.)
    uint32_t r1a, r1b, r2a, r2b;
    tf2x32(k2a, k2b, 0u, 0u, r1a, r1b);
    tf2x32(k2a, k2b, 0u, 1u, r2a, r2b);

    k_init<<<40, 256>>>(W2, b2);
    k_scatter<<<(EE + 255) / 256, 256>>>(dkg, k1a, k1b);
    k_select<<<(ND + 7) / 8, 256>>>();
    k_score_gemm<<<(ND * SAMP) / 64, 128>>>(drug_emb, rel_emb, W1, b1, dkg);
    k_neigh<<<(ND + 7) / 8, 256>>>(dkg, tail_emb, r1a, r1b, r2a, r2b);
    k_y<<<(ND + 63) / 64, 256>>>(drug_emb, Wc, bc);
    k_bn<<<1, 64>>>(gamma, beta);
    k_out<<<(out_size + 255) / 256, 256>>>(HFE, X, (float*)d_out, out_size);
}

// round 14
// speedup vs baseline: 1.6847x; 1.0002x over previous
#include <cuda_runtime.h>
#include <stdint.h>

// ---------------------------------------------------------------------------
// Problem constants
// ---------------------------------------------------------------------------
#define EE   1000000
#define ND   10000
#define NT   20000
#define NRR  100
#define DD   64
#define SAMP 16
#define CAP  512         // per-head bucket capacity (deg ~ Poisson(100))
#define OVF  65536       // overflow list capacity (guaranteed-correct fallback)

// ---------------------------------------------------------------------------
// Scratch (no allocs allowed -> __device__ globals)
// ---------------------------------------------------------------------------
__device__ unsigned long long g_keys[(size_t)ND * CAP];   // 41 MB bucketed keys
__device__ int                g_cur[ND];                  // bucket cursors == degrees
__device__ int                g_ovf_cnt;
__device__ int                g_ovf_head[OVF];
__device__ unsigned long long g_ovf_key[OVF];
__device__ unsigned int       g_sel[ND * SAMP];           // selected edge ids
__device__ float              g_neigh[ND * DD];
__device__ float              g_y[ND * DD];
__device__ float              g_w2rs[DD];
__device__ float              g_b2sum[1];
__device__ double             g_sum[DD];
__device__ double             g_sumsq[DD];
__device__ float              g_scale[DD];
__device__ float              g_shift[DD];

// ---------------------------------------------------------------------------
// Threefry-2x32 (20 rounds) — shared host/device
// ---------------------------------------------------------------------------
__host__ __device__ __forceinline__ void tf2x32(uint32_t k0, uint32_t k1,
                                                uint32_t x0, uint32_t x1,
                                                uint32_t& o0, uint32_t& o1)
{
    uint32_t ks[3];
    ks[0] = k0; ks[1] = k1; ks[2] = k0 ^ k1 ^ 0x1BD11BDAu;
    const int RA[4] = {13, 15, 26, 6};
    const int RB[4] = {17, 29, 16, 24};
    x0 += ks[0]; x1 += ks[1];
#pragma unroll
    for (int g = 0; g < 5; ++g) {
        const int* R = (g & 1) ? RB : RA;
#pragma unroll
        for (int i = 0; i < 4; ++i) {
            x0 += x1;
            int r = R[i];
            x1 = (x1 << r) | (x1 >> (32 - r));
            x1 ^= x0;
        }
        x0 += ks[(g + 1) % 3];
        x1 += ks[(g + 2) % 3] + (uint32_t)(g + 1);
    }
    o0 = x0; o1 = x1;
}

__host__ __device__ __forceinline__ uint32_t jax_bits32(uint32_t k0, uint32_t k1,
                                                        uint32_t hi, uint32_t lo)
{
    uint32_t o0, o1;
    tf2x32(k0, k1, hi, lo, o0, o1);
    return o0 ^ o1;   // _threefry_random_bits_partitionable, bit_width==32
}

// ---------------------------------------------------------------------------
// Packed f32x2 FMA helpers (FFMA2 — 2x fp32 throughput on sm_103a)
// ---------------------------------------------------------------------------
__device__ __forceinline__ unsigned long long pk2(float lo, float hi)
{
    unsigned long long r;
    asm("mov.b64 %0, {%1, %2};" : "=l"(r) : "f"(lo), "f"(hi));
    return r;
}
__device__ __forceinline__ void fma2(unsigned long long& acc,
                                     unsigned long long a, unsigned long long b)
{
    asm("fma.rn.f32x2 %0, %1, %2, %0;" : "+l"(acc) : "l"(a), "l"(b));
}
__device__ __forceinline__ float2 up2(unsigned long long v)
{
    float lo, hi;
    asm("mov.b64 {%0, %1}, %2;" : "=f"(lo), "=f"(hi) : "l"(v));
    return make_float2(lo, hi);
}
__device__ __forceinline__ float sigm(float x)
{
    return 1.f / (1.f + __expf(-x));
}

// ---------------------------------------------------------------------------
// K0: zero cursors, rowsum W2, b2 sum
// ---------------------------------------------------------------------------
__global__ void k_init(const float* __restrict__ W2, const float* __restrict__ b2)
{
    int i = blockIdx.x * blockDim.x + threadIdx.x;
    if (i < ND) g_cur[i] = 0;
    if (i < DD) {
        float s = 0.f;
        for (int j = 0; j < DD; ++j) s += W2[i * DD + j];
        g_w2rs[i] = s;
        g_sum[i] = 0.0; g_sumsq[i] = 0.0;
    }
    if (i == 0) {
        float s = 0.f;
        for (int j = 0; j < DD; ++j) s += b2[j];
        g_b2sum[0] = s;
        g_ovf_cnt = 0;
    }
}

// ---------------------------------------------------------------------------
// K1: single-pass bucketed scatter of sort keys (bits>>9, edge_id).
//     Bucket cursor doubles as the degree count.
// ---------------------------------------------------------------------------
__global__ void k_scatter(const int* __restrict__ dkg, uint32_t ka, uint32_t kb)
{
    int e = blockIdx.x * blockDim.x + threadIdx.x;
    if (e >= EE) return;
    int head = dkg[3 * e];
    uint32_t bits = jax_bits32(ka, kb, 0u, (uint32_t)e);
    uint32_t m = bits >> 9;  // float order == (bits>>9) order
    unsigned long long key =
        ((unsigned long long)m << 32) | (unsigned long long)(uint32_t)e;
    int pos = atomicAdd(&g_cur[head], 1);
    if (pos < CAP) {
        g_keys[(size_t)head * CAP + pos] = key;
    } else {
        int o = atomicAdd(&g_ovf_cnt, 1);
        if (o < OVF) { g_ovf_head[o] = head; g_ovf_key[o] = key; }
    }
}

// ---------------------------------------------------------------------------
// K2: warp-per-drug: select the 16 smallest keys (== rank<16 in lexsort order)
//     and record their edge ids in sorted order.
// ---------------------------------------------------------------------------
__global__ void __launch_bounds__(256) k_select()
{
    int wid = threadIdx.x >> 5, lane = threadIdx.x & 31;
    int d = blockIdx.x * 8 + wid;
    if (d >= ND) return;
    int deg = g_cur[d];
    if (deg <= 0) return;
    int n = min(deg, CAP);
    int oc = min(g_ovf_cnt, OVF);
    int nkeep = min(deg, SAMP);
    const unsigned long long* bucket = g_keys + (size_t)d * CAP;

    unsigned long long prev = 0;
    bool small = (n <= 192) && (oc == 0);
    unsigned long long kreg[6];
    if (small) {
#pragma unroll
        for (int q = 0; q < 6; ++q) {
            int p = lane + q * 32;
            kreg[q] = (p < n) ? bucket[p] : ~0ull;
        }
    }
    for (int it = 0; it < nkeep; ++it) {
        unsigned long long best = ~0ull;
        if (small) {
#pragma unroll
            for (int q = 0; q < 6; ++q) {
                unsigned long long kk = kreg[q];
                if ((it == 0 || kk > prev) && kk < best) best = kk;
            }
        } else {
            for (int p = lane; p < n; p += 32) {
                unsigned long long kk = bucket[p];
                if ((it == 0 || kk > prev) && kk < best) best = kk;
            }
            for (int o = lane; o < oc; o += 32) {
                if (g_ovf_head[o] == d) {
                    unsigned long long kk = g_ovf_key[o];
                    if ((it == 0 || kk > prev) && kk < best) best = kk;
                }
            }
        }
#pragma unroll
        for (int s = 16; s; s >>= 1) {
            unsigned long long o = __shfl_xor_sync(0xffffffffu, best, s);
            if (o < best) best = o;
        }
        prev = best;
        if (lane == 0) g_sel[d * SAMP + it] = (unsigned int)best;
    }
}

// ---------------------------------------------------------------------------
// K3: fused score GEMM + neighbor aggregation.
//     Block = 128 threads = 128 selected edges = 8 whole drugs.
//     Phase 1: load W1 (16KB) + stage h = drug⊙rel transposed into sH[k][edge]
//              (1 thread per edge; tail id kept in register).
//     Phase 2: 8 output-groups x 16 edge-groups; 8 edges x 8 outputs per
//              thread, f32x2-packed accumulators.
//              Per k-step: 2 LDS.128 (A) + 2 LDS.128 (W) + 32 FFMA2.
//     Phase 3: scores+tails staged into (retired) sW region; per-drug
//              neigh[d] = sum score_i * tail_emb[tail_i] (+ deg<16 extras).
// ---------------------------------------------------------------------------
__global__ void __launch_bounds__(128) k_score_neigh(const float* __restrict__ drug_emb,
                                                     const float* __restrict__ rel_emb,
                                                     const float* __restrict__ W1,
                                                     const float* __restrict__ b1,
                                                     const float* __restrict__ tail_emb,
                                                     const int* __restrict__ dkg,
                                                     uint32_t ua, uint32_t ub,
                                                     uint32_t uc, uint32_t ud)
{
    __shared__ float sH[DD * 128];  // 32 KB: h transposed, sH[k*128 + edge]
    __shared__ float sW[DD * DD];   // 16 KB: W1 row-major; reused after GEMM
    float* sScore = sW;             //   alias (post-GEMM): 128 scores
    int*   sTail  = (int*)(sW + 128); // alias (post-GEMM): 128 tail ids

    int t = threadIdx.x;
    int base = blockIdx.x * 128;    // first selected-slot index of this block

    // ---- load W1 into smem ----
#pragma unroll
    for (int i = t; i < DD * DD / 4; i += 128)
        ((float4*)sW)[i] = ((const float4*)W1)[i];

    // ---- Phase 1: gather + stage (1 thread per edge) ----
    int my_tail;
    {
        int idx = base + t;             // < ND*SAMP (1250*128 == 160000)
        int d = idx >> 4, i = idx & 15;
        int nk = min(g_cur[d], SAMP);
        bool valid = (i < nk);
        unsigned int e = valid ? g_sel[idx] : 0u;
        my_tail = dkg[3 * (int)e + 1];
        int rel  = dkg[3 * (int)e + 2];
        const float4* dp = (const float4*)(drug_emb + (size_t)d * DD);
        const float4* rp = (const float4*)(rel_emb + (size_t)rel * DD);
#pragma unroll
        for (int q = 0; q < 16; ++q) {
            float4 a = dp[q], b = rp[q];
            sH[(4 * q + 0) * 128 + t] = a.x * b.x;
            sH[(4 * q + 1) * 128 + t] = a.y * b.y;
            sH[(4 * q + 2) * 128 + t] = a.z * b.z;
            sH[(4 * q + 3) * 128 + t] = a.w * b.w;
        }
    }
    __syncthreads();

    // ---- Phase 2: 8x8 microtile GEMM ----
    int tx = t & 7;        // output group: outputs tx*8 .. tx*8+7
    int ty = t >> 3;       // edge group:   edges  ty*8 .. ty*8+7

    unsigned long long acc[8][4];
    {
        const float4* bp = (const float4*)(b1 + tx * 8);
        float4 b0 = bp[0], b4 = bp[1];
        unsigned long long i0 = pk2(b0.x, b0.y), i1 = pk2(b0.z, b0.w);
        unsigned long long i2 = pk2(b4.x, b4.y), i3 = pk2(b4.z, b4.w);
#pragma unroll
        for (int e = 0; e < 8; ++e) {
            acc[e][0] = i0; acc[e][1] = i1; acc[e][2] = i2; acc[e][3] = i3;
        }
    }

#pragma unroll 2
    for (int kk = 0; kk < DD; ++kk) {
        float4 a0 = *(const float4*)&sH[kk * 128 + ty * 8];
        float4 a1 = *(const float4*)&sH[kk * 128 + ty * 8 + 4];
        ulonglong2 w0 = *(const ulonglong2*)(sW + kk * DD + tx * 8);
        ulonglong2 w1 = *(const ulonglong2*)(sW + kk * DD + tx * 8 + 4);
        float ae[8] = {a0.x, a0.y, a0.z, a0.w, a1.x, a1.y, a1.z, a1.w};
#pragma unroll
        for (int e = 0; e < 8; ++e) {
            unsigned long long aa = pk2(ae[e], ae[e]);
            fma2(acc[e][0], aa, w0.x);
            fma2(acc[e][1], aa, w0.y);
            fma2(acc[e][2], aa, w1.x);
            fma2(acc[e][3], aa, w1.y);
        }
    }

    // ---- Epilogue: sigmoid · rowsum(W2), reduce across 8 output groups ----
    float rs[8];
    {
        const float4* rp = (const float4*)(g_w2rs + tx * 8);
        float4 r0 = rp[0], r1 = rp[1];
        rs[0] = r0.x; rs[1] = r0.y; rs[2] = r0.z; rs[3] = r0.w;
        rs[4] = r1.x; rs[5] = r1.y; rs[6] = r1.z; rs[7] = r1.w;
    }
    float b2s = g_b2sum[0];

    float myscore[8];
#pragma unroll
    for (int e = 0; e < 8; ++e) {
        float pe = 0.f;
#pragma unroll
        for (int p = 0; p < 4; ++p) {
            float2 uv = up2(acc[e][p]);
            pe += sigm(uv.x) * rs[2 * p] + sigm(uv.y) * rs[2 * p + 1];
        }
        pe += __shfl_xor_sync(0xffffffffu, pe, 1);
        pe += __shfl_xor_sync(0xffffffffu, pe, 2);
        pe += __shfl_xor_sync(0xffffffffu, pe, 4);
        myscore[e] = pe + b2s;
    }

    __syncthreads();   // mainloop smem reads done; safe to retire sW
    if (tx == 0) {
#pragma unroll
        for (int e = 0; e < 8; ++e) sScore[ty * 8 + e] = myscore[e];
    }
    sTail[t] = my_tail;
    __syncthreads();

    // ---- Phase 3: per-drug neighbor aggregation ----
    {
        int dl = t >> 4;                 // local drug 0..7
        int cg = t & 15;                 // column group: cols cg*4 .. cg*4+3
        int d = (base >> 4) + dl;        // global drug
        int deg = g_cur[d];
        int nk = min(deg, SAMP);
        float4 a = make_float4(0.f, 0.f, 0.f, 0.f);
        for (int i = 0; i < nk; ++i) {
            float sc = sScore[dl * SAMP + i];
            int   tl = sTail[dl * SAMP + i];
            float4 tv = *(const float4*)(tail_emb + (size_t)tl * DD + cg * 4);
            a.x += sc * tv.x; a.y += sc * tv.y;
            a.z += sc * tv.z; a.w += sc * tv.w;
        }
        if (deg > 0 && deg < SAMP) {
            int need = SAMP - deg;
            const uint32_t span = 2147483647u;
            for (int si = 0; si < need; ++si) {
                uint32_t flat = (uint32_t)(d * SAMP + si);
                uint32_t hi  = jax_bits32(ua, ub, 0u, flat);
                uint32_t lo2 = jax_bits32(uc, ud, 0u, flat);
                unsigned long long offv =
                    ((unsigned long long)(hi % span) * 2ull + (lo2 % span)) % span;
                unsigned int j = (unsigned int)(offv % (unsigned int)deg);
                float sc = sScore[dl * SAMP + j];
                int   tl = sTail[dl * SAMP + j];
                float4 tv = *(const float4*)(tail_emb + (size_t)tl * DD + cg * 4);
                a.x += sc * tv.x; a.y += sc * tv.y;
                a.z += sc * tv.z; a.w += sc * tv.w;
            }
        }
        *(float4*)(g_neigh + (size_t)d * DD + cg * 4) = a;
    }
}

// ---------------------------------------------------------------------------
// K5: y = [drug_emb | neigh] @ Wc + bc, plus per-column sum/sumsq for BN
// ---------------------------------------------------------------------------
__global__ void __launch_bounds__(256) k_y(const float* __restrict__ drug_emb,
                                           const float* __restrict__ Wc,
                                           const float* __restrict__ bc)
{
    __shared__ float sWc[2 * DD * DD];   // 32 KB
    __shared__ float sb[DD];
    __shared__ float red[256];
    int t = threadIdx.x;
    for (int i = t; i < 2 * DD * DD; i += 256) sWc[i] = Wc[i];
    if (t < DD) sb[t] = bc[t];
    __syncthreads();

    int col = t & 63, grp = t >> 6;
    int base = blockIdx.x * 64;
    float s1 = 0.f, s2 = 0.f;
    for (int rr = 0; rr < 16; ++rr) {
        int row = base + rr * 4 + grp;
        if (row < ND) {
            const float* de = drug_emb + (size_t)row * DD;
            const float* ne = g_neigh + (size_t)row * DD;
            float a = sb[col];
#pragma unroll
            for (int i = 0; i < DD; ++i) a += de[i] * sWc[i * DD + col];
#pragma unroll
            for (int i = 0; i < DD; ++i) a += ne[i] * sWc[(DD + i) * DD + col];
            g_y[row * DD + col] = a;
            s1 += a; s2 += a * a;
        }
    }
    red[t] = s1; __syncthreads();
    if (t < 64)
        atomicAdd(&g_sum[t], (double)(red[t] + red[t + 64] + red[t + 128] + red[t + 192]));
    __syncthreads();
    red[t] = s2; __syncthreads();
    if (t < 64)
        atomicAdd(&g_sumsq[t], (double)(red[t] + red[t + 64] + red[t + 128] + red[t + 192]));
}

// ---------------------------------------------------------------------------
// K6: fold BN stats into scale/shift
// ---------------------------------------------------------------------------
__global__ void k_bn(const float* __restrict__ gamma, const float* __restrict__ beta)
{
    int t = threadIdx.x;
    if (t < DD) {
        double mean = g_sum[t] / (double)ND;
        double var = g_sumsq[t] / (double)ND - mean * mean;
        float sc = gamma[t] * rsqrtf((float)var + 1e-5f);
        g_scale[t] = sc;
        g_shift[t] = beta[t] - (float)mean * sc;
    }
}

// ---------------------------------------------------------------------------
// K7: assemble output (HFEmbeding | normalized y | X)
// ---------------------------------------------------------------------------
__global__ void k_out(const float* __restrict__ hfe, const float* __restrict__ X,
                      float* __restrict__ out, int out_size)
{
    int i = blockIdx.x * blockDim.x + threadIdx.x;
    if (i >= out_size) return;
    if (i < ND * DD) {
        out[i] = hfe[i];
    } else if (i < 2 * ND * DD) {
        int j = i - ND * DD;
        int c = j & 63;
        out[i] = g_y[j] * g_scale[c] + g_shift[c];
    } else {
        out[i] = X[i - 2 * ND * DD];
    }
}

// ---------------------------------------------------------------------------
// Launcher
// ---------------------------------------------------------------------------
extern "C" void kernel_launch(void* const* d_in, const int* in_sizes, int n_in,
                              void* d_out, int out_size)
{
    const float* HFE      = (const float*)d_in[0];
    const float* X        = (const float*)d_in[1];
    const float* drug_emb = (const float*)d_in[2];
    const float* rel_emb  = (const float*)d_in[3];
    const float* tail_emb = (const float*)d_in[4];
    const float* W1       = (const float*)d_in[5];
    const float* b1       = (const float*)d_in[6];
    const float* W2       = (const float*)d_in[7];
    const float* b2       = (const float*)d_in[8];
    const float* Wc       = (const float*)d_in[9];
    const float* bc       = (const float*)d_in[10];
    const float* gamma    = (const float*)d_in[11];
    const float* beta     = (const float*)d_in[12];
    const int*   dkg      = (const int*)d_in[13];

    // Derive jax.random.key(42) subkeys on host (pure arithmetic).
    uint32_t key0 = 0u, key1 = 42u;
    uint32_t k1a, k1b, k2a, k2b;
    tf2x32(key0, key1, 0u, 0u, k1a, k1b);   // fold-like split -> subkey 0
    tf2x32(key0, key1, 0u, 1u, k2a, k2b);   // fold-like split -> subkey 1
    // split(k2) for the randint double-draw (dead path: deg>=16 a.s.)
    uint32_t r1a, r1b, r2a, r2b;
    tf2x32(k2a, k2b, 0u, 0u, r1a, r1b);
    tf2x32(k2a, k2b, 0u, 1u, r2a, r2b);

    k_init<<<40, 256>>>(W2, b2);
    k_scatter<<<(EE + 255) / 256, 256>>>(dkg, k1a, k1b);
    k_select<<<(ND + 7) / 8, 256>>>();
    k_score_neigh<<<(ND * SAMP) / 128, 128>>>(drug_emb, rel_emb, W1, b1,
                                              tail_emb, dkg, r1a, r1b, r2a, r2b);
    k_y<<<(ND + 63) / 64, 256>>>(drug_emb, Wc, bc);
    k_bn<<<1, 64>>>(gamma, beta);
    k_out<<<(out_size + 255) / 256, 256>>>(HFE, X, (float*)d_out, out_size);
}

// round 17
// speedup vs baseline: 1.7285x; 1.0261x over previous
#include <cuda_runtime.h>
#include <stdint.h>

// ---------------------------------------------------------------------------
// Problem constants
// ---------------------------------------------------------------------------
#define EE   1000000
#define ND   10000
#define NT   20000
#define NRR  100
#define DD   64
#define SAMP 16
#define CAP  512         // per-head bucket capacity (deg ~ Poisson(100))
#define OVF  65536       // overflow list capacity (guaranteed-correct fallback)

// ---------------------------------------------------------------------------
// Scratch (no allocs allowed -> __device__ globals)
// ---------------------------------------------------------------------------
__device__ unsigned long long g_keys[(size_t)ND * CAP];   // 41 MB bucketed keys
__device__ int                g_cur[ND];                  // bucket cursors == degrees
__device__ int                g_ovf_cnt;
__device__ int                g_ovf_head[OVF];
__device__ unsigned long long g_ovf_key[OVF];
__device__ unsigned int       g_sel[ND * SAMP];           // selected edge ids
__device__ float              g_neigh[ND * DD];
__device__ float              g_y[ND * DD];
__device__ float              g_w2rs[DD];
__device__ float              g_b2sum[1];
__device__ double             g_sum[DD];
__device__ double             g_sumsq[DD];
__device__ float              g_scale[DD];
__device__ float              g_shift[DD];

// ---------------------------------------------------------------------------
// Threefry-2x32 (20 rounds) — shared host/device
// ---------------------------------------------------------------------------
__host__ __device__ __forceinline__ void tf2x32(uint32_t k0, uint32_t k1,
                                                uint32_t x0, uint32_t x1,
                                                uint32_t& o0, uint32_t& o1)
{
    uint32_t ks[3];
    ks[0] = k0; ks[1] = k1; ks[2] = k0 ^ k1 ^ 0x1BD11BDAu;
    const int RA[4] = {13, 15, 26, 6};
    const int RB[4] = {17, 29, 16, 24};
    x0 += ks[0]; x1 += ks[1];
#pragma unroll
    for (int g = 0; g < 5; ++g) {
        const int* R = (g & 1) ? RB : RA;
#pragma unroll
        for (int i = 0; i < 4; ++i) {
            x0 += x1;
            int r = R[i];
            x1 = (x1 << r) | (x1 >> (32 - r));
            x1 ^= x0;
        }
        x0 += ks[(g + 1) % 3];
        x1 += ks[(g + 2) % 3] + (uint32_t)(g + 1);
    }
    o0 = x0; o1 = x1;
}

__host__ __device__ __forceinline__ uint32_t jax_bits32(uint32_t k0, uint32_t k1,
                                                        uint32_t hi, uint32_t lo)
{
    uint32_t o0, o1;
    tf2x32(k0, k1, hi, lo, o0, o1);
    return o0 ^ o1;   // _threefry_random_bits_partitionable, bit_width==32
}

// ---------------------------------------------------------------------------
// Packed f32x2 FMA helpers (FFMA2 — 2x fp32 throughput on sm_103a)
// ---------------------------------------------------------------------------
__device__ __forceinline__ unsigned long long pk2(float lo, float hi)
{
    unsigned long long r;
    asm("mov.b64 %0, {%1, %2};" : "=l"(r) : "f"(lo), "f"(hi));
    return r;
}
__device__ __forceinline__ void fma2(unsigned long long& acc,
                                     unsigned long long a, unsigned long long b)
{
    asm("fma.rn.f32x2 %0, %1, %2, %0;" : "+l"(acc) : "l"(a), "l"(b));
}
__device__ __forceinline__ float2 up2(unsigned long long v)
{
    float lo, hi;
    asm("mov.b64 {%0, %1}, %2;" : "=f"(lo), "=f"(hi) : "l"(v));
    return make_float2(lo, hi);
}
__device__ __forceinline__ float sigm(float x)
{
    return 1.f / (1.f + __expf(-x));
}

// ---------------------------------------------------------------------------
// K0: zero cursors, rowsum W2, b2 sum
// ---------------------------------------------------------------------------
__global__ void k_init(const float* __restrict__ W2, const float* __restrict__ b2)
{
    int i = blockIdx.x * blockDim.x + threadIdx.x;
    if (i < ND) g_cur[i] = 0;
    if (i < DD) {
        float s = 0.f;
        for (int j = 0; j < DD; ++j) s += W2[i * DD + j];
        g_w2rs[i] = s;
        g_sum[i] = 0.0; g_sumsq[i] = 0.0;
    }
    if (i == 0) {
        float s = 0.f;
        for (int j = 0; j < DD; ++j) s += b2[j];
        g_b2sum[0] = s;
        g_ovf_cnt = 0;
    }
}

// ---------------------------------------------------------------------------
// K1: bucketed scatter of sort keys (bits>>9, edge_id), 4 edges per thread.
//     Coalesced 3x int4 read of dkg; independent threefry chains give MLP=4.
// ---------------------------------------------------------------------------
__global__ void k_scatter(const int* __restrict__ dkg, uint32_t ka, uint32_t kb)
{
    int base = (blockIdx.x * blockDim.x + threadIdx.x) * 4;
    if (base >= EE) return;
    const int4* p = (const int4*)(dkg + 3 * base);   // 48B = 3 x int4
    int4 w0 = p[0], w1 = p[1], w2 = p[2];
    int heads[4] = {w0.x, w0.w, w1.z, w2.y};

    uint32_t bits[4];
#pragma unroll
    for (int q = 0; q < 4; ++q)
        bits[q] = jax_bits32(ka, kb, 0u, (uint32_t)(base + q));

#pragma unroll
    for (int q = 0; q < 4; ++q) {
        uint32_t m = bits[q] >> 9;   // float order == (bits>>9) order
        unsigned long long key =
            ((unsigned long long)m << 32) | (unsigned long long)(uint32_t)(base + q);
        int head = heads[q];
        int pos = atomicAdd(&g_cur[head], 1);
        if (pos < CAP) {
            g_keys[(size_t)head * CAP + pos] = key;
        } else {
            int o = atomicAdd(&g_ovf_cnt, 1);
            if (o < OVF) { g_ovf_head[o] = head; g_ovf_key[o] = key; }
        }
    }
}

// ---------------------------------------------------------------------------
// K2: warp-per-drug: select the 16 smallest keys (== rank<16 in lexsort order)
//     and record their edge ids in sorted order.
// ---------------------------------------------------------------------------
__global__ void __launch_bounds__(256) k_select()
{
    int wid = threadIdx.x >> 5, lane = threadIdx.x & 31;
    int d = blockIdx.x * 8 + wid;
    if (d >= ND) return;
    int deg = g_cur[d];
    if (deg <= 0) return;
    int n = min(deg, CAP);
    int oc = min(g_ovf_cnt, OVF);
    int nkeep = min(deg, SAMP);
    const unsigned long long* bucket = g_keys + (size_t)d * CAP;

    unsigned long long prev = 0;
    bool small = (n <= 192) && (oc == 0);
    unsigned long long kreg[6];
    if (small) {
#pragma unroll
        for (int q = 0; q < 6; ++q) {
            int p = lane + q * 32;
            kreg[q] = (p < n) ? bucket[p] : ~0ull;
        }
    }
    for (int it = 0; it < nkeep; ++it) {
        unsigned long long best = ~0ull;
        if (small) {
#pragma unroll
            for (int q = 0; q < 6; ++q) {
                unsigned long long kk = kreg[q];
                if ((it == 0 || kk > prev) && kk < best) best = kk;
            }
        } else {
            for (int p = lane; p < n; p += 32) {
                unsigned long long kk = bucket[p];
                if ((it == 0 || kk > prev) && kk < best) best = kk;
            }
            for (int o = lane; o < oc; o += 32) {
                if (g_ovf_head[o] == d) {
                    unsigned long long kk = g_ovf_key[o];
                    if ((it == 0 || kk > prev) && kk < best) best = kk;
                }
            }
        }
#pragma unroll
        for (int s = 16; s; s >>= 1) {
            unsigned long long o = __shfl_xor_sync(0xffffffffu, best, s);
            if (o < best) best = o;
        }
        prev = best;
        if (lane == 0) g_sel[d * SAMP + it] = (unsigned int)best;
    }
}

// ---------------------------------------------------------------------------
// K3: fused score GEMM + neighbor aggregation.
//     Block = 128 threads = 64 selected edges = 4 whole drugs.
//     Edge-pair trick: sH keeps edges contiguous, so one LDS.128 of 4
//     consecutive edge values is two packed f32x2 A-operands (no dup movs);
//     only W is duplicated (4 movs per k-step). 4 pairs x 4 outputs per
//     thread: per k-step 3 LDS + 4 movs + 16 FFMA2.
// ---------------------------------------------------------------------------
__global__ void __launch_bounds__(128) k_score_neigh(const float* __restrict__ drug_emb,
                                                     const float* __restrict__ rel_emb,
                                                     const float* __restrict__ W1,
                                                     const float* __restrict__ b1,
                                                     const float* __restrict__ tail_emb,
                                                     const int* __restrict__ dkg,
                                                     uint32_t ua, uint32_t ub,
                                                     uint32_t uc, uint32_t ud)
{
    __shared__ float sH[DD * 64];   // 16 KB: h transposed, sH[k*64 + edge]
    __shared__ float sW[DD * DD];   // 16 KB: W1 row-major
    __shared__ float sScore[64];
    __shared__ int   sTail[64];

    int t = threadIdx.x;
    int base = blockIdx.x * 64;     // first selected-slot index of this block

    // ---- load W1 into smem ----
#pragma unroll
    for (int i = t; i < DD * DD / 4; i += 128)
        ((float4*)sW)[i] = ((const float4*)W1)[i];

    // ---- Phase 1: gather + stage (2 threads per edge) ----
    {
        int le = t >> 1;            // local edge 0..63
        int half = t & 1;           // which 32 of the 64 dims
        int idx = base + le;        // < ND*SAMP (2500*64 == 160000)
        int d = idx >> 4, i = idx & 15;
        int nk = min(g_cur[d], SAMP);
        bool valid = (i < nk);
        unsigned int e = valid ? g_sel[idx] : 0u;
        int tl  = dkg[3 * (int)e + 1];
        int rel = dkg[3 * (int)e + 2];
        if (half == 0) sTail[le] = tl;
        const float4* dp = (const float4*)(drug_emb + (size_t)d * DD) + half * 8;
        const float4* rp = (const float4*)(rel_emb + (size_t)rel * DD) + half * 8;
#pragma unroll
        for (int q = 0; q < 8; ++q) {
            float4 a = dp[q], b = rp[q];
            int k0 = half * 32 + 4 * q;
            sH[(k0 + 0) * 64 + le] = a.x * b.x;
            sH[(k0 + 1) * 64 + le] = a.y * b.y;
            sH[(k0 + 2) * 64 + le] = a.z * b.z;
            sH[(k0 + 3) * 64 + le] = a.w * b.w;
        }
    }
    __syncthreads();

    // ---- Phase 2: 4-pairs x 4-outputs microtile GEMM ----
    int tx = t & 15;       // output group: outputs tx*4 .. tx*4+3
    int ty = t >> 4;       // edge group:   edges  ty*8 .. ty*8+7 (pairs ty*4..)

    unsigned long long acc[4][4];   // [pair][out], lo=edge 2p, hi=edge 2p+1
    {
        float4 bv = *(const float4*)(b1 + tx * 4);
        unsigned long long i0 = pk2(bv.x, bv.x), i1 = pk2(bv.y, bv.y);
        unsigned long long i2 = pk2(bv.z, bv.z), i3 = pk2(bv.w, bv.w);
#pragma unroll
        for (int p = 0; p < 4; ++p) {
            acc[p][0] = i0; acc[p][1] = i1; acc[p][2] = i2; acc[p][3] = i3;
        }
    }

#pragma unroll 4
    for (int kk = 0; kk < DD; ++kk) {
        ulonglong2 A0 = *(const ulonglong2*)&sH[kk * 64 + ty * 8];     // pairs 0,1
        ulonglong2 A1 = *(const ulonglong2*)&sH[kk * 64 + ty * 8 + 4]; // pairs 2,3
        float4 wv = *(const float4*)(sW + kk * DD + tx * 4);
        unsigned long long w0 = pk2(wv.x, wv.x), w1 = pk2(wv.y, wv.y);
        unsigned long long w2 = pk2(wv.z, wv.z), w3 = pk2(wv.w, wv.w);
        unsigned long long ap[4] = {A0.x, A0.y, A1.x, A1.y};
#pragma unroll
        for (int p = 0; p < 4; ++p) {
            fma2(acc[p][0], ap[p], w0);
            fma2(acc[p][1], ap[p], w1);
            fma2(acc[p][2], ap[p], w2);
            fma2(acc[p][3], ap[p], w3);
        }
    }

    // ---- Epilogue: sigmoid · rowsum(W2), reduce across 16 output groups ----
    float4 rsv = *(const float4*)(g_w2rs + tx * 4);
    float b2s = g_b2sum[0];

#pragma unroll
    for (int p = 0; p < 4; ++p) {
        float2 s = make_float2(0.f, 0.f);
        float2 u;
        u = up2(acc[p][0]); s.x += sigm(u.x) * rsv.x; s.y += sigm(u.y) * rsv.x;
        u = up2(acc[p][1]); s.x += sigm(u.x) * rsv.y; s.y += sigm(u.y) * rsv.y;
        u = up2(acc[p][2]); s.x += sigm(u.x) * rsv.z; s.y += sigm(u.y) * rsv.z;
        u = up2(acc[p][3]); s.x += sigm(u.x) * rsv.w; s.y += sigm(u.y) * rsv.w;
        unsigned long long sp = pk2(s.x, s.y);
#pragma unroll
        for (int sh = 1; sh < 16; sh <<= 1) {
            unsigned long long o = __shfl_xor_sync(0xffffffffu, sp, sh);
            float2 a = up2(sp), b = up2(o);
            sp = pk2(a.x + b.x, a.y + b.y);
        }
        if (tx == 0) {
            float2 sv = up2(sp);
            sScore[ty * 8 + 2 * p]     = sv.x + b2s;
            sScore[ty * 8 + 2 * p + 1] = sv.y + b2s;
        }
    }
    __syncthreads();

    // ---- Phase 3: per-drug neighbor aggregation (warp per drug) ----
    {
        int dl = t >> 5;                 // local drug 0..3
        int lane = t & 31;               // col pair: cols 2*lane, 2*lane+1
        int d = (base >> 4) + dl;        // global drug
        int deg = g_cur[d];
        int nk = min(deg, SAMP);
        float ax = 0.f, ay = 0.f;
        for (int i = 0; i < nk; ++i) {
            float sc = sScore[dl * SAMP + i];
            int   tl = sTail[dl * SAMP + i];
            float2 te = *(const float2*)(tail_emb + (size_t)tl * DD + 2 * lane);
            ax += sc * te.x; ay += sc * te.y;
        }
        if (deg > 0 && deg < SAMP) {
            int need = SAMP - deg;
            const uint32_t span = 2147483647u;
            for (int si = 0; si < need; ++si) {
                uint32_t flat = (uint32_t)(d * SAMP + si);
                uint32_t hi  = jax_bits32(ua, ub, 0u, flat);
                uint32_t lo2 = jax_bits32(uc, ud, 0u, flat);
                unsigned long long offv =
                    ((unsigned long long)(hi % span) * 2ull + (lo2 % span)) % span;
                unsigned int j = (unsigned int)(offv % (unsigned int)deg);
                float sc = sScore[dl * SAMP + j];
                int   tl = sTail[dl * SAMP + j];
                float2 te = *(const float2*)(tail_emb + (size_t)tl * DD + 2 * lane);
                ax += sc * te.x; ay += sc * te.y;
            }
        }
        g_neigh[(size_t)d * DD + 2 * lane]     = ax;
        g_neigh[(size_t)d * DD + 2 * lane + 1] = ay;
    }
}

// ---------------------------------------------------------------------------
// K5: y = [drug_emb | neigh] @ Wc + bc, plus per-column sum/sumsq for BN
// ---------------------------------------------------------------------------
__global__ void __launch_bounds__(256) k_y(const float* __restrict__ drug_emb,
                                           const float* __restrict__ Wc,
                                           const float* __restrict__ bc)
{
    __shared__ float sWc[2 * DD * DD];   // 32 KB
    __shared__ float sb[DD];
    __shared__ float red[256];
    int t = threadIdx.x;
    for (int i = t; i < 2 * DD * DD; i += 256) sWc[i] = Wc[i];
    if (t < DD) sb[t] = bc[t];
    __syncthreads();

    int col = t & 63, grp = t >> 6;
    int base = blockIdx.x * 64;
    float s1 = 0.f, s2 = 0.f;
    for (int rr = 0; rr < 16; ++rr) {
        int row = base + rr * 4 + grp;
        if (row < ND) {
            const float* de = drug_emb + (size_t)row * DD;
            const float* ne = g_neigh + (size_t)row * DD;
            float a = sb[col];
#pragma unroll
            for (int i = 0; i < DD; ++i) a += de[i] * sWc[i * DD + col];
#pragma unroll
            for (int i = 0; i < DD; ++i) a += ne[i] * sWc[(DD + i) * DD + col];
            g_y[row * DD + col] = a;
            s1 += a; s2 += a * a;
        }
    }
    red[t] = s1; __syncthreads();
    if (t < 64)
        atomicAdd(&g_sum[t], (double)(red[t] + red[t + 64] + red[t + 128] + red[t + 192]));
    __syncthreads();
    red[t] = s2; __syncthreads();
    if (t < 64)
        atomicAdd(&g_sumsq[t], (double)(red[t] + red[t + 64] + red[t + 128] + red[t + 192]));
}

// ---------------------------------------------------------------------------
// K6: fold BN stats into scale/shift
// ---------------------------------------------------------------------------
__global__ void k_bn(const float* __restrict__ gamma, const float* __restrict__ beta)
{
    int t = threadIdx.x;
    if (t < DD) {
        double mean = g_sum[t] / (double)ND;
        double var = g_sumsq[t] / (double)ND - mean * mean;
        float sc = gamma[t] * rsqrtf((float)var + 1e-5f);
        g_scale[t] = sc;
        g_shift[t] = beta[t] - (float)mean * sc;
    }
}

// ---------------------------------------------------------------------------
// K7: assemble output (HFEmbeding | normalized y | X)
// ---------------------------------------------------------------------------
__global__ void k_out(const float* __restrict__ hfe, const float* __restrict__ X,
                      float* __restrict__ out, int out_size)
{
    int i = blockIdx.x * blockDim.x + threadIdx.x;
    if (i >= out_size) return;
    if (i < ND * DD) {
        out[i] = hfe[i];
    } else if (i < 2 * ND * DD) {
        int j = i - ND * DD;
        int c = j & 63;
        out[i] = g_y[j] * g_scale[c] + g_shift[c];
    } else {
        out[i] = X[i - 2 * ND * DD];
    }
}

// ---------------------------------------------------------------------------
// Launcher
// ---------------------------------------------------------------------------
extern "C" void kernel_launch(void* const* d_in, const int* in_sizes, int n_in,
                              void* d_out, int out_size)
{
    const float* HFE      = (const float*)d_in[0];
    const float* X        = (const float*)d_in[1];
    const float* drug_emb = (const float*)d_in[2];
    const float* rel_emb  = (const float*)d_in[3];
    const float* tail_emb = (const float*)d_in[4];
    const float* W1       = (const float*)d_in[5];
    const float* b1       = (const float*)d_in[6];
    const float* W2       = (const float*)d_in[7];
    const float* b2       = (const float*)d_in[8];
    const float* Wc       = (const float*)d_in[9];
    const float* bc       = (const float*)d_in[10];
    const float* gamma    = (const float*)d_in[11];
    const float* beta     = (const float*)d_in[12];
    const int*   dkg      = (const int*)d_in[13];

    // Derive jax.random.key(42) subkeys on host (pure arithmetic).
    uint32_t key0 = 0u, key1 = 42u;
    uint32_t k1a, k1b, k2a, k2b;
    tf2x32(key0, key1, 0u, 0u, k1a, k1b);   // fold-like split -> subkey 0
    tf2x32(key0, key1, 0u, 1u, k2a, k2b);   // fold-like split -> subkey 1
    // split(k2) for the randint double-draw (dead path: deg>=16 a.s.)
    uint32_t r1a, r1b, r2a, r2b;
    tf2x32(k2a, k2b, 0u, 0u, r1a, r1b);
    tf2x32(k2a, k2b, 0u, 1u, r2a, r2b);

    k_init<<<40, 256>>>(W2, b2);
    k_scatter<<<(EE / 4 + 255) / 256, 256>>>(dkg, k1a, k1b);
    k_select<<<(ND + 7) / 8, 256>>>();
    k_score_neigh<<<(ND * SAMP) / 64, 128>>>(drug_emb, rel_emb, W1, b1,
                                             tail_emb, dkg, r1a, r1b, r2a, r2b);
    k_y<<<(ND + 63) / 64, 256>>>(drug_emb, Wc, bc);
    k_bn<<<1, 64>>>(gamma, beta);
    k_out<<<(out_size + 255) / 256, 256>>>(HFE, X, (float*)d_out, out_size);
}